// round 2
// baseline (speedup 1.0000x reference)
#include <cuda_runtime.h>

#define PNUM 16320
#define BATCH 32
#define NCLS 21
#define TOPK 500
#define CONF_THV 0.01f
#define NMS_THV 0.45f
#define OBJ_THV 0.01f

// ---- device scratch (no allocations allowed) ----
__device__ float4 g_boxes[BATCH * PNUM];                 // decoded boxes (x1,y1,x2,y2)
__device__ float  g_scores[BATCH * (NCLS - 1) * PNUM];   // arm-masked scores, [B][20][P]

// ---- shared memory layout (bytes) ----
#define OFF_SCORES 0        // 16320*4 = 65280
#define OFF_HIST   65280    // 257*4 -> pad to 1056
#define OFF_MISC   66336    // 64
#define OFF_SELS   66400    // 512*4
#define OFF_SELI   68448    // 512*4
#define SMEM_TOTAL 70496
// phase B (overlays score region, which is dead by then)
#define OFF_BOX    0        // 512*16 = 8192
#define OFF_AREA   8192     // 512*4
#define OFF_MAT    10240    // 512*16*4 = 32768
#define OFF_ROWS   43008    // 2500*4 = 10000 (pad)

// =====================================================================
// Kernel 1: cascaded decode + arm-masked score transpose [B][P][C] -> [B][C-1][P]
// =====================================================================
__global__ void prep_kernel(const float* __restrict__ arm_loc,
                            const float* __restrict__ arm_conf,
                            const float* __restrict__ odm_loc,
                            const float* __restrict__ odm_conf,
                            const float* __restrict__ priors) {
    int idx = blockIdx.x * blockDim.x + threadIdx.x;
    if (idx >= BATCH * PNUM) return;
    int b = idx / PNUM;
    int p = idx % PNUM;

    float pcx = priors[p * 4 + 0];
    float pcy = priors[p * 4 + 1];
    float pw  = priors[p * 4 + 2];
    float ph  = priors[p * 4 + 3];

    const float* al = arm_loc + (size_t)idx * 4;
    const float* ol = odm_loc + (size_t)idx * 4;

    // arm decode -> center_size (replicating exact op order of reference)
    float cx = pcx + al[0] * 0.1f * pw;
    float cy = pcy + al[1] * 0.1f * ph;
    float w  = pw * expf(al[2] * 0.2f);
    float h  = ph * expf(al[3] * 0.2f);
    float mnx = cx - w * 0.5f;
    float mny = cy - h * 0.5f;
    float mxx = mnx + w;
    float mxy = mny + h;
    float dcx = (mxx + mnx) * 0.5f;
    float dcy = (mxy + mny) * 0.5f;
    float dw  = mxx - mnx;
    float dh  = mxy - mny;

    // odm decode with cascaded "priors"
    float cx2 = dcx + ol[0] * 0.1f * dw;
    float cy2 = dcy + ol[1] * 0.1f * dh;
    float w2  = dw * expf(ol[2] * 0.2f);
    float h2  = dh * expf(ol[3] * 0.2f);
    float x1 = cx2 - w2 * 0.5f;
    float y1 = cy2 - h2 * 0.5f;
    float x2 = x1 + w2;
    float y2 = y1 + h2;
    g_boxes[idx] = make_float4(x1, y1, x2, y2);

    bool armpass = arm_conf[(size_t)idx * 2 + 1] > OBJ_THV;
    const float* oc = odm_conf + (size_t)idx * NCLS;
#pragma unroll
    for (int c = 1; c < NCLS; ++c) {
        float v = armpass ? oc[c] : 0.0f;
        g_scores[((size_t)(b * (NCLS - 1) + (c - 1))) * PNUM + p] = v;
    }
}

// =====================================================================
// Kernel 2: one block per (image, class): exact top-500 radix-select
// (64-bit key = score bits ‖ ~index, matches lax.top_k tie semantics),
// bitonic sort 512, suppression bitmatrix, serial greedy NMS by warp 0.
// =====================================================================
__global__ void __launch_bounds__(512) task_kernel(float* __restrict__ out) {
    extern __shared__ char smraw[];
    float*    s_scores = (float*)(smraw + OFF_SCORES);
    unsigned* hist     = (unsigned*)(smraw + OFF_HIST);
    unsigned* misc     = (unsigned*)(smraw + OFF_MISC);
    float*    sel_s    = (float*)(smraw + OFF_SELS);
    int*      sel_i    = (int*)(smraw + OFF_SELI);
    float4*   bx4      = (float4*)(smraw + OFF_BOX);
    float*    s_area   = (float*)(smraw + OFF_AREA);
    unsigned* mat      = (unsigned*)(smraw + OFF_MAT);
    float*    rows     = (float*)(smraw + OFF_ROWS);

    const int tid = threadIdx.x;
    const int b   = blockIdx.x / NCLS;
    const int cl  = blockIdx.x % NCLS;
    float* outp = out + (size_t)(b * NCLS + cl) * (TOPK * 5);

    if (cl == 0) {  // background class: all zeros
        for (int e = tid; e < TOPK * 5; e += 512) outp[e] = 0.0f;
        return;
    }

    const float* sp = g_scores + (size_t)(b * (NCLS - 1) + (cl - 1)) * PNUM;

    if (tid == 0) { misc[0] = 0u; misc[1] = 0u; }
    __syncthreads();

    // ---- load scores into smem + count valid ----
    int local = 0;
    for (int j = tid; j < PNUM; j += 512) {
        float s = sp[j];
        s_scores[j] = s;
        if (s > CONF_THV) local++;
    }
#pragma unroll
    for (int o = 16; o; o >>= 1) local += __shfl_down_sync(0xFFFFFFFFu, local, o);
    if ((tid & 31) == 0) atomicAdd(&misc[0], (unsigned)local);
    __syncthreads();

    const int K = min((int)misc[0], TOPK);
    if (K == 0) {
        for (int e = tid; e < TOPK * 5; e += 512) outp[e] = 0.0f;
        return;
    }

    // ---- radix select: find the K-th largest 64-bit key exactly ----
    if (tid == 0) { misc[2] = 0u; misc[3] = 0u; misc[4] = (unsigned)K; misc[5] = 0u; }
    __syncthreads();

    for (int bp = 7; bp >= 0; --bp) {
        if (misc[5]) break;  // uniform (post-sync)
        for (int hh = tid; hh < 257; hh += 512) hist[hh] = 0u;
        __syncthreads();
        unsigned long long pfx = ((unsigned long long)misc[3] << 32) | misc[2];
        for (int j = tid; j < PNUM; j += 512) {
            float s = s_scores[j];
            int bin = 256;
            if (s > CONF_THV) {
                unsigned long long key =
                    ((unsigned long long)__float_as_uint(s) << 32) |
                    (unsigned long long)(0xFFFFFFFFu - (unsigned)j);
                bool m = (bp == 7) ||
                         ((key >> ((bp + 1) * 8)) == (pfx >> ((bp + 1) * 8)));
                if (m) bin = (int)((key >> (bp * 8)) & 0xFFull);
            }
            unsigned grp = __match_any_sync(0xFFFFFFFFu, bin);
            if (((unsigned)tid & 31u) == (unsigned)(__ffs(grp) - 1) && bin < 256)
                atomicAdd(&hist[bin], (unsigned)__popc(grp));
        }
        __syncthreads();
        if (tid == 0) {
            unsigned rem = misc[4];
            unsigned cum = 0;
            int bsel = 0;
            for (int hh = 255; hh >= 0; --hh) {
                cum += hist[hh];
                if (cum >= rem) { bsel = hh; break; }
            }
            unsigned take = rem - (cum - hist[bsel]);
            unsigned long long pfx2 = (((unsigned long long)misc[3] << 32) | misc[2]) |
                                      ((unsigned long long)bsel << (bp * 8));
            misc[2] = (unsigned)pfx2;
            misc[3] = (unsigned)(pfx2 >> 32);
            misc[4] = take;
            if (take == hist[bsel]) misc[5] = 1u;  // all prefix-equal keys selected
        }
        __syncthreads();
    }
    __syncthreads();
    const unsigned long long T = ((unsigned long long)misc[3] << 32) | misc[2];

    // ---- compact the exactly-K selected keys ----
    for (int j = tid; j < PNUM; j += 512) {
        float s = s_scores[j];
        bool sel = false;
        if (s > CONF_THV) {
            unsigned long long key =
                ((unsigned long long)__float_as_uint(s) << 32) |
                (unsigned long long)(0xFFFFFFFFu - (unsigned)j);
            sel = (key >= T);
        }
        unsigned m = __ballot_sync(0xFFFFFFFFu, sel);
        unsigned base = 0;
        if ((tid & 31) == 0 && m) base = atomicAdd(&misc[1], (unsigned)__popc(m));
        base = __shfl_sync(0xFFFFFFFFu, base, 0);
        if (sel) {
            unsigned pos = base + __popc(m & ((1u << (tid & 31)) - 1u));
            sel_s[pos] = s;
            sel_i[pos] = j;
        }
    }
    __syncthreads();
    if (tid >= K) { sel_s[tid] = -1.0f; sel_i[tid] = 0x40000000 + tid; }
    __syncthreads();

    // ---- bitonic sort 512 entries: descending score, ties by smaller index ----
    for (unsigned k = 2; k <= 512; k <<= 1) {
        for (unsigned jj = k >> 1; jj > 0; jj >>= 1) {
            unsigned i = (unsigned)tid;
            unsigned ixj = i ^ jj;
            if (ixj > i) {
                float si = sel_s[i], sx = sel_s[ixj];
                int ii = sel_i[i], ix = sel_i[ixj];
                bool g = (sx > si) || (sx == si && ix < ii);  // elem[ixj] strictly before elem[i]
                bool asc = ((i & k) == 0);
                if (asc ? g : !g) {
                    sel_s[i] = sx; sel_s[ixj] = si;
                    sel_i[i] = ix; sel_i[ixj] = ii;
                }
            }
            __syncthreads();
        }
    }

    // ---- gather boxes (scores region now dead; overlay phase-B arrays) ----
    {
        float4 bb = make_float4(0.f, 0.f, 0.f, 0.f);
        float a = 0.f;
        if (tid < K) {
            bb = g_boxes[(size_t)b * PNUM + sel_i[tid]];
            a = (bb.z - bb.x) * (bb.w - bb.y);
        }
        __syncthreads();  // everyone done reading sorted sel_i slot contention-free
        bx4[tid] = bb;
        s_area[tid] = a;
    }
    for (int e = tid; e < TOPK * 5; e += 512) rows[e] = 0.0f;
    __syncthreads();

    // ---- suppression bitmatrix: bit j of row i set iff !(iou(i,j) <= TH) ----
    {
        float4 bi = bx4[tid];
        float ai = s_area[tid];
        unsigned wbits = 0u;
#pragma unroll 4
        for (int j = 0; j < 512; ++j) {
            float4 bj = bx4[j];
            float xx1 = fmaxf(bi.x, bj.x);
            float yy1 = fmaxf(bi.y, bj.y);
            float xx2 = fminf(bi.z, bj.z);
            float yy2 = fminf(bi.w, bj.w);
            float iw = fmaxf(xx2 - xx1, 0.0f);
            float ih = fmaxf(yy2 - yy1, 0.0f);
            float inter = iw * ih;
            float denom = (s_area[j] - inter) + ai;  // union; strictly > 0 here
            bool sup = !(inter <= NMS_THV * denom);  // == !(iou <= TH), NaN-safe
            wbits |= (sup ? 1u : 0u) << (j & 31);
            if ((j & 31) == 31) { mat[tid * 16 + (j >> 5)] = wbits; wbits = 0u; }
        }
    }
    __syncthreads();

    // ---- greedy NMS: warp 0, bitmask walk (lane l<16 owns 32 candidates) ----
    if (tid < 32) {
        unsigned am = 0u;
        if (tid < 16) {
            int n = K - tid * 32;
            am = (n >= 32) ? 0xFFFFFFFFu : (n > 0 ? ((1u << n) - 1u) : 0u);
        }
        for (int t = 0; t < TOPK; ++t) {
            unsigned bal = __ballot_sync(0xFFFFFFFFu, am != 0u);
            if (!bal) break;  // remaining rows already zero
            int w0 = __ffs(bal) - 1;
            unsigned word = __shfl_sync(0xFFFFFFFFu, am, w0);
            int pv = (w0 << 5) + __ffs(word) - 1;
            if (tid == 0) {
                float4 bp = bx4[pv];
                rows[t * 5 + 0] = sel_s[pv];
                rows[t * 5 + 1] = bp.x;
                rows[t * 5 + 2] = bp.y;
                rows[t * 5 + 3] = bp.z;
                rows[t * 5 + 4] = bp.w;
            }
            unsigned mrow = (tid < 16) ? mat[pv * 16 + tid] : 0u;
            am &= ~mrow;
            if (tid == w0) am &= ~(1u << (pv & 31));
        }
    }
    __syncthreads();

    // ---- coalesced writeout ----
    for (int e = tid; e < TOPK * 5; e += 512) outp[e] = rows[e];
}

extern "C" void kernel_launch(void* const* d_in, const int* in_sizes, int n_in,
                              void* d_out, int out_size) {
    const float* arm_loc  = (const float*)d_in[0];
    const float* arm_conf = (const float*)d_in[1];
    const float* odm_loc  = (const float*)d_in[2];
    const float* odm_conf = (const float*)d_in[3];
    const float* priors   = (const float*)d_in[4];
    float* out = (float*)d_out;

    cudaFuncSetAttribute(task_kernel, cudaFuncAttributeMaxDynamicSharedMemorySize,
                         SMEM_TOTAL);

    int total = BATCH * PNUM;
    prep_kernel<<<(total + 255) / 256, 256>>>(arm_loc, arm_conf, odm_loc, odm_conf,
                                              priors);
    task_kernel<<<BATCH * NCLS, 512, SMEM_TOTAL>>>(out);
}

// round 3
// speedup vs baseline: 1.4742x; 1.4742x over previous
#include <cuda_runtime.h>

#define PNUM 16320
#define BATCH 32
#define NCLS 21
#define TOPK 500
#define CONF_THV 0.01f
#define NMS_THV 0.45f
#define OBJ_THV 0.01f

// ---- device scratch (no allocations allowed) ----
__device__ float4 g_boxes[BATCH * PNUM];                 // decoded boxes (x1,y1,x2,y2)
__device__ float  g_scores[BATCH * (NCLS - 1) * PNUM];   // arm-masked scores, [B][20][P]

// ---- shared memory layout (bytes) ----
#define OFF_HIST   0        // 256*4 = 1024
#define OFF_MISC   1024     // 64
#define OFF_SELS   1088     // 512*4 = 2048
#define OFF_SELI   3136     // 512*4 = 2048
#define OFF_BOX    5184     // 512*16 = 8192 (16B aligned)
#define OFF_AREA   13376    // 512*4 = 2048
#define OFF_MAT    15424    // 512*16*4 = 32768
#define OFF_PORD   48192    // 512*4 = 2048
#define SMEM_TOTAL 50240    // -> 4 blocks/SM (64 warps = max occupancy)

// =====================================================================
// Kernel 1: cascaded decode + arm-masked score transpose [B][P][C] -> [B][C-1][P]
// =====================================================================
__global__ void prep_kernel(const float* __restrict__ arm_loc,
                            const float* __restrict__ arm_conf,
                            const float* __restrict__ odm_loc,
                            const float* __restrict__ odm_conf,
                            const float* __restrict__ priors) {
    int idx = blockIdx.x * blockDim.x + threadIdx.x;
    if (idx >= BATCH * PNUM) return;
    int b = idx / PNUM;
    int p = idx % PNUM;

    float pcx = priors[p * 4 + 0];
    float pcy = priors[p * 4 + 1];
    float pw  = priors[p * 4 + 2];
    float ph  = priors[p * 4 + 3];

    const float* al = arm_loc + (size_t)idx * 4;
    const float* ol = odm_loc + (size_t)idx * 4;

    // arm decode -> center_size (replicating exact op order of reference)
    float cx = pcx + al[0] * 0.1f * pw;
    float cy = pcy + al[1] * 0.1f * ph;
    float w  = pw * expf(al[2] * 0.2f);
    float h  = ph * expf(al[3] * 0.2f);
    float mnx = cx - w * 0.5f;
    float mny = cy - h * 0.5f;
    float mxx = mnx + w;
    float mxy = mny + h;
    float dcx = (mxx + mnx) * 0.5f;
    float dcy = (mxy + mny) * 0.5f;
    float dw  = mxx - mnx;
    float dh  = mxy - mny;

    // odm decode with cascaded "priors"
    float cx2 = dcx + ol[0] * 0.1f * dw;
    float cy2 = dcy + ol[1] * 0.1f * dh;
    float w2  = dw * expf(ol[2] * 0.2f);
    float h2  = dh * expf(ol[3] * 0.2f);
    float x1 = cx2 - w2 * 0.5f;
    float y1 = cy2 - h2 * 0.5f;
    float x2 = x1 + w2;
    float y2 = y1 + h2;
    g_boxes[idx] = make_float4(x1, y1, x2, y2);

    bool armpass = arm_conf[(size_t)idx * 2 + 1] > OBJ_THV;
    const float* oc = odm_conf + (size_t)idx * NCLS;
#pragma unroll
    for (int c = 1; c < NCLS; ++c) {
        float v = armpass ? oc[c] : 0.0f;
        g_scores[((size_t)(b * (NCLS - 1) + (c - 1))) * PNUM + p] = v;
    }
}

// =====================================================================
// Kernel 2: one block per (image, class): exact top-500 radix-select on
// 64-bit keys (score bits || ~index == lax.top_k tie semantics; scores
// streamed from global each pass — DRAM/L2 idle, smem freed for occupancy),
// bitonic sort 512, UPPER-TRIANGLE suppression bitmatrix (greedy NMS on a
// sorted list only ever consults j > pivot), serial bitmask NMS by warp 0.
// =====================================================================
__global__ void __launch_bounds__(512) task_kernel(float* __restrict__ out) {
    extern __shared__ char smraw[];
    unsigned* hist   = (unsigned*)(smraw + OFF_HIST);
    unsigned* misc   = (unsigned*)(smraw + OFF_MISC);
    float*    sel_s  = (float*)(smraw + OFF_SELS);
    int*      sel_i  = (int*)(smraw + OFF_SELI);
    float4*   bx4    = (float4*)(smraw + OFF_BOX);
    float*    s_area = (float*)(smraw + OFF_AREA);
    unsigned* mat    = (unsigned*)(smraw + OFF_MAT);
    int*      pord   = (int*)(smraw + OFF_PORD);

    const int tid = threadIdx.x;
    const int b   = blockIdx.x / NCLS;
    const int cl  = blockIdx.x % NCLS;
    float* outp = out + (size_t)(b * NCLS + cl) * (TOPK * 5);

    if (cl == 0) {  // background class: all zeros
        for (int e = tid; e < TOPK * 5; e += 512) outp[e] = 0.0f;
        return;
    }

    const float* __restrict__ sp =
        g_scores + (size_t)(b * (NCLS - 1) + (cl - 1)) * PNUM;

    // ---- radix pass A (byte 7 of key = top byte of score bits) + count ----
    if (tid < 256) hist[tid] = 0u;
    if (tid == 0) { misc[1] = 0u; misc[5] = 0u; }
    __syncthreads();

    for (int j = tid; j < PNUM; j += 512) {
        float s = __ldg(&sp[j]);
        int bin = (s > CONF_THV) ? (int)(__float_as_uint(s) >> 24) : 256;
        unsigned grp = __match_any_sync(0xFFFFFFFFu, bin);
        if (((unsigned)tid & 31u) == (unsigned)(__ffs(grp) - 1) && bin < 256)
            atomicAdd(&hist[bin], (unsigned)__popc(grp));
    }
    __syncthreads();

    if (tid == 0) {
        unsigned total = 0;
        for (int hh = 0; hh < 256; ++hh) total += hist[hh];
        unsigned K = total < TOPK ? total : TOPK;
        misc[6] = K;
        if (K > 0) {
            unsigned cum = 0; int bsel = 0;
            for (int hh = 255; hh >= 0; --hh) {
                cum += hist[hh];
                if (cum >= K) { bsel = hh; break; }
            }
            unsigned take = K - (cum - hist[bsel]);
            unsigned long long pfx = (unsigned long long)bsel << 56;
            misc[2] = (unsigned)pfx;
            misc[3] = (unsigned)(pfx >> 32);
            misc[4] = take;
            if (take == hist[bsel]) misc[5] = 1u;
        }
    }
    __syncthreads();

    const int K = (int)misc[6];
    if (K == 0) {
        for (int e = tid; e < TOPK * 5; e += 512) outp[e] = 0.0f;
        return;
    }

    // ---- remaining radix passes (scores re-read from global; L2-resident) ----
    for (int bp = 6; bp >= 0; --bp) {
        if (misc[5]) break;  // uniform (read after sync)
        if (tid < 256) hist[tid] = 0u;
        __syncthreads();
        unsigned long long pfx = ((unsigned long long)misc[3] << 32) | misc[2];
        for (int j = tid; j < PNUM; j += 512) {
            float s = __ldg(&sp[j]);
            int bin = 256;
            if (s > CONF_THV) {
                unsigned long long key =
                    ((unsigned long long)__float_as_uint(s) << 32) |
                    (unsigned long long)(0xFFFFFFFFu - (unsigned)j);
                if ((key >> ((bp + 1) * 8)) == (pfx >> ((bp + 1) * 8)))
                    bin = (int)((key >> (bp * 8)) & 0xFFull);
            }
            unsigned grp = __match_any_sync(0xFFFFFFFFu, bin);
            if (((unsigned)tid & 31u) == (unsigned)(__ffs(grp) - 1) && bin < 256)
                atomicAdd(&hist[bin], (unsigned)__popc(grp));
        }
        __syncthreads();
        if (tid == 0) {
            unsigned rem = misc[4];
            unsigned cum = 0; int bsel = 0;
            for (int hh = 255; hh >= 0; --hh) {
                cum += hist[hh];
                if (cum >= rem) { bsel = hh; break; }
            }
            unsigned take = rem - (cum - hist[bsel]);
            unsigned long long pfx2 = (((unsigned long long)misc[3] << 32) | misc[2]) |
                                      ((unsigned long long)bsel << (bp * 8));
            misc[2] = (unsigned)pfx2;
            misc[3] = (unsigned)(pfx2 >> 32);
            misc[4] = take;
            if (take == hist[bsel]) misc[5] = 1u;
        }
        __syncthreads();
    }
    __syncthreads();
    const unsigned long long T = ((unsigned long long)misc[3] << 32) | misc[2];

    // ---- compact the exactly-K selected keys ----
    for (int j = tid; j < PNUM; j += 512) {
        float s = __ldg(&sp[j]);
        bool sel = false;
        if (s > CONF_THV) {
            unsigned long long key =
                ((unsigned long long)__float_as_uint(s) << 32) |
                (unsigned long long)(0xFFFFFFFFu - (unsigned)j);
            sel = (key >= T);
        }
        unsigned m = __ballot_sync(0xFFFFFFFFu, sel);
        unsigned base = 0;
        if ((tid & 31) == 0 && m) base = atomicAdd(&misc[1], (unsigned)__popc(m));
        base = __shfl_sync(0xFFFFFFFFu, base, 0);
        if (sel) {
            unsigned pos = base + __popc(m & ((1u << (tid & 31)) - 1u));
            sel_s[pos] = s;
            sel_i[pos] = j;
        }
    }
    __syncthreads();
    if (tid >= K) { sel_s[tid] = -1.0f; sel_i[tid] = 0x40000000 + tid; }
    __syncthreads();

    // ---- bitonic sort 512 entries: descending score, ties by smaller index ----
    for (unsigned k = 2; k <= 512; k <<= 1) {
        for (unsigned jj = k >> 1; jj > 0; jj >>= 1) {
            unsigned i = (unsigned)tid;
            unsigned ixj = i ^ jj;
            if (ixj > i) {
                float si = sel_s[i], sx = sel_s[ixj];
                int ii = sel_i[i], ix = sel_i[ixj];
                bool g = (sx > si) || (sx == si && ix < ii);
                bool asc = ((i & k) == 0);
                if (asc ? g : !g) {
                    sel_s[i] = sx; sel_s[ixj] = si;
                    sel_i[i] = ix; sel_i[ixj] = ii;
                }
            }
            __syncthreads();
        }
    }

    // ---- gather boxes into smem ----
    {
        float4 bb = make_float4(0.f, 0.f, 0.f, 0.f);
        float a = 0.f;
        if (tid < K) {
            bb = g_boxes[(size_t)b * PNUM + sel_i[tid]];
            a = (bb.z - bb.x) * (bb.w - bb.y);
        }
        bx4[tid] = bb;
        s_area[tid] = a;
    }
    __syncthreads();

    // ---- UPPER-TRIANGLE suppression bitmatrix ----
    // Greedy NMS on a descending-sorted list always picks the first active
    // candidate, so suppression row pv is only ever applied to j > pv.
    {
        const int w0 = tid >> 5;
        for (int w = 0; w < w0; ++w) mat[tid * 16 + w] = 0u;  // never consulted live
        float4 bi = bx4[tid];
        float ai = s_area[tid];
        for (int w = w0; w < 16; ++w) {
            unsigned bits = 0u;
#pragma unroll 8
            for (int k = 0; k < 32; ++k) {
                int j = (w << 5) + k;
                float4 bj = bx4[j];
                float xx1 = fmaxf(bi.x, bj.x);
                float yy1 = fmaxf(bi.y, bj.y);
                float xx2 = fminf(bi.z, bj.z);
                float yy2 = fminf(bi.w, bj.w);
                float iw = fmaxf(xx2 - xx1, 0.0f);
                float ih = fmaxf(yy2 - yy1, 0.0f);
                float inter = iw * ih;
                float denom = (s_area[j] - inter) + ai;  // union; > 0 for real boxes
                bool sup = !(inter <= NMS_THV * denom);  // == !(iou <= TH)
                bits |= (sup ? 1u : 0u) << k;
            }
            mat[tid * 16 + w] = bits;
        }
    }
    __syncthreads();

    // ---- greedy NMS: warp 0, bitmask walk (lane l<16 owns 32 candidates) ----
    if (tid < 32) {
        unsigned am = 0u;
        if (tid < 16) {
            int n = K - tid * 32;
            am = (n >= 32) ? 0xFFFFFFFFu : (n > 0 ? ((1u << n) - 1u) : 0u);
        }
        int cnt = 0;
        for (int t = 0; t < TOPK; ++t) {
            unsigned bal = __ballot_sync(0xFFFFFFFFu, am != 0u);
            if (!bal) break;
            int wsel = __ffs(bal) - 1;
            unsigned word = __shfl_sync(0xFFFFFFFFu, am, wsel);
            int pv = (wsel << 5) + __ffs(word) - 1;
            if (tid == 0) pord[t] = pv;
            cnt = t + 1;
            unsigned mrow = (tid < 16) ? mat[pv * 16 + tid] : 0u;
            am &= ~mrow;
            if (tid == wsel) am &= ~(1u << (pv & 31));
        }
        if (tid == 0) misc[7] = (unsigned)cnt;
    }
    __syncthreads();

    // ---- writeout directly from sel/bx4 via pivot order ----
    const int cnt = (int)misc[7];
    for (int t = tid; t < TOPK; t += 512) {
        float r0 = 0.f, r1 = 0.f, r2 = 0.f, r3 = 0.f, r4 = 0.f;
        if (t < cnt) {
            int p = pord[t];
            float4 bb = bx4[p];
            r0 = sel_s[p]; r1 = bb.x; r2 = bb.y; r3 = bb.z; r4 = bb.w;
        }
        outp[t * 5 + 0] = r0;
        outp[t * 5 + 1] = r1;
        outp[t * 5 + 2] = r2;
        outp[t * 5 + 3] = r3;
        outp[t * 5 + 4] = r4;
    }
}

extern "C" void kernel_launch(void* const* d_in, const int* in_sizes, int n_in,
                              void* d_out, int out_size) {
    const float* arm_loc  = (const float*)d_in[0];
    const float* arm_conf = (const float*)d_in[1];
    const float* odm_loc  = (const float*)d_in[2];
    const float* odm_conf = (const float*)d_in[3];
    const float* priors   = (const float*)d_in[4];
    float* out = (float*)d_out;

    cudaFuncSetAttribute(task_kernel, cudaFuncAttributeMaxDynamicSharedMemorySize,
                         SMEM_TOTAL);

    int total = BATCH * PNUM;
    prep_kernel<<<(total + 255) / 256, 256>>>(arm_loc, arm_conf, odm_loc, odm_conf,
                                              priors);
    task_kernel<<<BATCH * NCLS, 512, SMEM_TOTAL>>>(out);
}